// round 5
// baseline (speedup 1.0000x reference)
#include <cuda_runtime.h>
#include <cstdint>

#define NE    8192
#define DIM   128
#define PMAX  5
#define NNODE 512
#define TOTAL (NNODE * NNODE)

#define THREADS     1024
#define DOT_CTAS    128
#define G_CTAS      64                     // gather CTAs: 64 x 1024 x 4 pairs
#define PAIRS_THR   4
#define TBL_BYTES   (PMAX * NE * 4)        // 163840
#define CHUNKS      4
#define CHUNK_BYTES (TBL_BYTES / CHUNKS)   // 40960

// Precomputed dot products, layout [p][e].
__device__ float g_dots[PMAX * NE];

__device__ __forceinline__ uint32_t smem_u32(const void* p) {
    return (uint32_t)__cvta_generic_to_shared(p);
}

// ---------------------------------------------------------------------------
// Kernel 1: dots[p][e] = sum_d emb[e][d] * ev[p][d]
// 128 CTAs x 1024 threads, warp handles 2 edges: single wave.
// ---------------------------------------------------------------------------
__global__ __launch_bounds__(THREADS) void edge_dot_kernel(
        const float* __restrict__ emb, const float* __restrict__ ev) {
    const int lane = threadIdx.x & 31;
    const int w    = threadIdx.x >> 5;
    const int e0   = (blockIdx.x * 32 + w) * 2;

    float4 evr[PMAX];
#pragma unroll
    for (int p = 0; p < PMAX; ++p)
        evr[p] = __ldg(((const float4*)ev) + p * (DIM / 4) + lane);

    float4 a0 = __ldg(((const float4*)emb) + (e0    ) * (DIM / 4) + lane);
    float4 a1 = __ldg(((const float4*)emb) + (e0 + 1) * (DIM / 4) + lane);

    float pa[PMAX], pb[PMAX];
#pragma unroll
    for (int p = 0; p < PMAX; ++p) {
        pa[p] = a0.x * evr[p].x + a0.y * evr[p].y + a0.z * evr[p].z + a0.w * evr[p].w;
        pb[p] = a1.x * evr[p].x + a1.y * evr[p].y + a1.z * evr[p].z + a1.w * evr[p].w;
    }
#pragma unroll
    for (int off = 16; off > 0; off >>= 1) {
#pragma unroll
        for (int p = 0; p < PMAX; ++p) {
            pa[p] += __shfl_xor_sync(0xffffffffu, pa[p], off);
            pb[p] += __shfl_xor_sync(0xffffffffu, pb[p], off);
        }
    }
    if (lane == 0) {
#pragma unroll
        for (int p = 0; p < PMAX; ++p) {
            g_dots[p * NE + e0]     = pa[p];
            g_dots[p * NE + e0 + 1] = pb[p];
        }
    }
}

// ---------------------------------------------------------------------------
// Kernel 2: 64 CTAs x 1024 threads x 4 pairs = 262144 exactly.
// Table bulk-copied into smem (issued ~immediately by tid0); paths loaded as
// five coalesced int4 per thread while the copy streams; no clusters.
// ---------------------------------------------------------------------------
__global__ __launch_bounds__(THREADS, 1) void gather_kernel(
        const int* __restrict__ paths, float* __restrict__ out) {
    extern __shared__ float s_dots[];               // 163840 bytes
    __shared__ __align__(8) unsigned long long mbar;

    const int tid  = threadIdx.x;
    const int slot = blockIdx.x * THREADS + tid;    // thread slot, 4 pairs each

    // --- paths prefetch: 5 x int4 = 20 consecutive ints (80B, coalesced) ---
    const int4* psrc = (const int4*)paths + slot * 5;
    int4 v0 = __ldg(psrc + 0);
    int4 v1 = __ldg(psrc + 1);
    int4 v2 = __ldg(psrc + 2);
    int4 v3 = __ldg(psrc + 3);
    int4 v4 = __ldg(psrc + 4);

    // --- mbarrier init + immediate bulk-copy issue (tid 0) ---
    const uint32_t mb = smem_u32(&mbar);
    if (tid == 0)
        asm volatile("mbarrier.init.shared.b64 [%0], 1;" :: "r"(mb));
    __syncthreads();
    if (tid == 0) {
        asm volatile("mbarrier.arrive.expect_tx.shared.b64 _, [%0], %1;"
                     :: "r"(mb), "r"((uint32_t)TBL_BYTES) : "memory");
        uint32_t    dst = smem_u32(s_dots);
        const char* src = (const char*)g_dots;
#pragma unroll
        for (int c = 0; c < CHUNKS; ++c) {
            asm volatile(
                "cp.async.bulk.shared::cta.global.mbarrier::complete_tx::bytes "
                "[%0], [%1], %2, [%3];"
                :: "r"(dst + c * CHUNK_BYTES), "l"(src + c * CHUNK_BYTES),
                   "r"((uint32_t)CHUNK_BYTES), "r"(mb)
                : "memory");
        }
    }

    // --- wait for table ---
    {
        uint32_t done;
        asm volatile(
            "{\n\t.reg .pred p;\n\t"
            "mbarrier.try_wait.parity.acquire.cta.shared::cta.b64 p, [%1], 0;\n\t"
            "selp.b32 %0, 1, 0, p;\n\t}"
            : "=r"(done) : "r"(mb) : "memory");
        while (!done) {
            asm volatile(
                "{\n\t.reg .pred p;\n\t"
                "mbarrier.try_wait.parity.acquire.cta.shared::cta.b64 p, [%1], 0, 0x989680;\n\t"
                "selp.b32 %0, 1, 0, p;\n\t}"
                : "=r"(done) : "r"(mb) : "memory");
        }
    }

    // --- gather + reduce: 4 pairs, indices unpacked from v0..v4 ---
    int e[20] = {v0.x, v0.y, v0.z, v0.w,  v1.x, v1.y, v1.z, v1.w,
                 v2.x, v2.y, v2.z, v2.w,  v3.x, v3.y, v3.z, v3.w,
                 v4.x, v4.y, v4.z, v4.w};

    float4 r;
    float* rr = (float*)&r;
#pragma unroll
    for (int j = 0; j < PAIRS_THR; ++j) {
        float acc = 0.0f; int cnt = 0;
#pragma unroll
        for (int p = 0; p < PMAX; ++p) {
            int ei = e[j * PMAX + p];
            if (ei >= 0) { acc += s_dots[p * NE + ei]; ++cnt; }
        }
        rr[j] = cnt ? acc / (float)cnt : 0.0f;
    }
    ((float4*)out)[slot] = r;
}

// ---------------------------------------------------------------------------
// Launch
// ---------------------------------------------------------------------------
extern "C" void kernel_launch(void* const* d_in, const int* in_sizes, int n_in,
                              void* d_out, int out_size) {
    const float* emb   = nullptr;
    const int*   paths = nullptr;
    const float* ev    = nullptr;
    for (int i = 0; i < n_in; ++i) {
        if (in_sizes[i] == NE * DIM)                  emb   = (const float*)d_in[i];
        else if (in_sizes[i] == NNODE * NNODE * PMAX) paths = (const int*)d_in[i];
        else if (in_sizes[i] == PMAX * DIM)           ev    = (const float*)d_in[i];
    }
    float* out = (float*)d_out;

    edge_dot_kernel<<<DOT_CTAS, THREADS>>>(emb, ev);

    cudaFuncSetAttribute(gather_kernel,
                         cudaFuncAttributeMaxDynamicSharedMemorySize,
                         TBL_BYTES);
    gather_kernel<<<G_CTAS, THREADS, TBL_BYTES>>>(paths, out);
}

// round 6
// speedup vs baseline: 1.0724x; 1.0724x over previous
#include <cuda_runtime.h>
#include <cstdint>

#define NE    8192
#define DIM   128
#define PMAX  5
#define NNODE 512
#define TOTAL (NNODE * NNODE)

#define THREADS      1024
#define DOT_CTAS     128
#define G_CTAS       128
#define PAIRS_CTA    (TOTAL / G_CTAS)        // 2048
#define TBL_BYTES    (PMAX * NE * 4)         // 163840
#define PATH_BYTES   (PAIRS_CTA * PMAX * 4)  // 40960
#define SMEM_BYTES   (TBL_BYTES + PATH_BYTES)// 204800
#define CHUNK_BYTES  40960

// Precomputed dot products, layout [p][e].
__device__ float g_dots[PMAX * NE];

__device__ __forceinline__ uint32_t smem_u32(const void* p) {
    return (uint32_t)__cvta_generic_to_shared(p);
}

__device__ __forceinline__ void mbar_wait(uint32_t mb) {
    uint32_t done;
    asm volatile(
        "{\n\t.reg .pred p;\n\t"
        "mbarrier.try_wait.parity.acquire.cta.shared::cta.b64 p, [%1], 0;\n\t"
        "selp.b32 %0, 1, 0, p;\n\t}"
        : "=r"(done) : "r"(mb) : "memory");
    while (!done) {
        asm volatile(
            "{\n\t.reg .pred p;\n\t"
            "mbarrier.try_wait.parity.acquire.cta.shared::cta.b64 p, [%1], 0, 0x989680;\n\t"
            "selp.b32 %0, 1, 0, p;\n\t}"
            : "=r"(done) : "r"(mb) : "memory");
    }
}

// ---------------------------------------------------------------------------
// Kernel 1: dots[p][e] = sum_d emb[e][d] * ev[p][d]
// 128 CTAs x 1024 threads, warp handles 2 edges: single wave.
// ---------------------------------------------------------------------------
__global__ __launch_bounds__(THREADS) void edge_dot_kernel(
        const float* __restrict__ emb, const float* __restrict__ ev) {
    const int lane = threadIdx.x & 31;
    const int w    = threadIdx.x >> 5;
    const int e0   = (blockIdx.x * 32 + w) * 2;

    float4 evr[PMAX];
#pragma unroll
    for (int p = 0; p < PMAX; ++p)
        evr[p] = __ldg(((const float4*)ev) + p * (DIM / 4) + lane);

    float4 a0 = __ldg(((const float4*)emb) + (e0    ) * (DIM / 4) + lane);
    float4 a1 = __ldg(((const float4*)emb) + (e0 + 1) * (DIM / 4) + lane);

    float pa[PMAX], pb[PMAX];
#pragma unroll
    for (int p = 0; p < PMAX; ++p) {
        pa[p] = a0.x * evr[p].x + a0.y * evr[p].y + a0.z * evr[p].z + a0.w * evr[p].w;
        pb[p] = a1.x * evr[p].x + a1.y * evr[p].y + a1.z * evr[p].z + a1.w * evr[p].w;
    }
#pragma unroll
    for (int off = 16; off > 0; off >>= 1) {
#pragma unroll
        for (int p = 0; p < PMAX; ++p) {
            pa[p] += __shfl_xor_sync(0xffffffffu, pa[p], off);
            pb[p] += __shfl_xor_sync(0xffffffffu, pb[p], off);
        }
    }
    if (lane == 0) {
#pragma unroll
        for (int p = 0; p < PMAX; ++p) {
            g_dots[p * NE + e0]     = pa[p];
            g_dots[p * NE + e0 + 1] = pb[p];
        }
    }
}

// ---------------------------------------------------------------------------
// Kernel 2: 128 CTAs x 1024 threads x 2 pairs = 262144 exactly.
// ZERO LDGs: both the dots table (160KB) and this CTA's edge_paths slice
// (40KB) are bulk-copied into smem. Threads read indices from smem and
// gather from the smem table.
// ---------------------------------------------------------------------------
__global__ __launch_bounds__(THREADS, 1) void gather_kernel(
        const int* __restrict__ paths, float* __restrict__ out) {
    extern __shared__ __align__(16) char smem[];
    float* s_dots  = (float*)smem;                   // 163840 B
    int*   s_paths = (int*)(smem + TBL_BYTES);       // 40960 B
    __shared__ __align__(8) unsigned long long mbar_p;  // paths ready
    __shared__ __align__(8) unsigned long long mbar_t;  // table ready

    const int tid = threadIdx.x;
    const uint32_t mbp = smem_u32(&mbar_p);
    const uint32_t mbt = smem_u32(&mbar_t);

    if (tid == 0) {
        asm volatile("mbarrier.init.shared.b64 [%0], 1;" :: "r"(mbp));
        asm volatile("mbarrier.init.shared.b64 [%0], 1;" :: "r"(mbt));
    }
    __syncthreads();

    if (tid == 0) {
        // paths slice first (smaller; indices ready early)
        asm volatile("mbarrier.arrive.expect_tx.shared.b64 _, [%0], %1;"
                     :: "r"(mbp), "r"((uint32_t)PATH_BYTES) : "memory");
        asm volatile(
            "cp.async.bulk.shared::cta.global.mbarrier::complete_tx::bytes "
            "[%0], [%1], %2, [%3];"
            :: "r"(smem_u32(s_paths)),
               "l"((const char*)paths + blockIdx.x * PATH_BYTES),
               "r"((uint32_t)PATH_BYTES), "r"(mbp)
            : "memory");

        // dots table (4 x 40KB)
        asm volatile("mbarrier.arrive.expect_tx.shared.b64 _, [%0], %1;"
                     :: "r"(mbt), "r"((uint32_t)TBL_BYTES) : "memory");
        uint32_t    dst = smem_u32(s_dots);
        const char* src = (const char*)g_dots;
#pragma unroll
        for (int c = 0; c < 4; ++c) {
            asm volatile(
                "cp.async.bulk.shared::cta.global.mbarrier::complete_tx::bytes "
                "[%0], [%1], %2, [%3];"
                :: "r"(dst + c * CHUNK_BYTES), "l"(src + c * CHUNK_BYTES),
                   "r"((uint32_t)CHUNK_BYTES), "r"(mbt)
                : "memory");
        }
    }

    // --- indices: thread t handles local pairs (2t, 2t+1) -> ints [10t,10t+10)
    mbar_wait(mbp);
    int e[2 * PMAX];
#pragma unroll
    for (int k = 0; k < 2 * PMAX; ++k)
        e[k] = s_paths[10 * tid + k];

    // --- table, then gather ---
    mbar_wait(mbt);

    float2 r;
    {
        float acc = 0.0f; int cnt = 0;
#pragma unroll
        for (int p = 0; p < PMAX; ++p) {
            int ei = e[p];
            if (ei >= 0) { acc += s_dots[p * NE + ei]; ++cnt; }
        }
        r.x = cnt ? acc / (float)cnt : 0.0f;
    }
    {
        float acc = 0.0f; int cnt = 0;
#pragma unroll
        for (int p = 0; p < PMAX; ++p) {
            int ei = e[PMAX + p];
            if (ei >= 0) { acc += s_dots[p * NE + ei]; ++cnt; }
        }
        r.y = cnt ? acc / (float)cnt : 0.0f;
    }
    ((float2*)out)[blockIdx.x * THREADS + tid] = r;
}

// ---------------------------------------------------------------------------
// Launch
// ---------------------------------------------------------------------------
extern "C" void kernel_launch(void* const* d_in, const int* in_sizes, int n_in,
                              void* d_out, int out_size) {
    const float* emb   = nullptr;
    const int*   paths = nullptr;
    const float* ev    = nullptr;
    for (int i = 0; i < n_in; ++i) {
        if (in_sizes[i] == NE * DIM)                  emb   = (const float*)d_in[i];
        else if (in_sizes[i] == NNODE * NNODE * PMAX) paths = (const int*)d_in[i];
        else if (in_sizes[i] == PMAX * DIM)           ev    = (const float*)d_in[i];
    }
    float* out = (float*)d_out;

    edge_dot_kernel<<<DOT_CTAS, THREADS>>>(emb, ev);

    cudaFuncSetAttribute(gather_kernel,
                         cudaFuncAttributeMaxDynamicSharedMemorySize,
                         SMEM_BYTES);
    gather_kernel<<<G_CTAS, THREADS, SMEM_BYTES>>>(paths, out);
}

// round 7
// speedup vs baseline: 1.1662x; 1.0875x over previous
#include <cuda_runtime.h>
#include <cstdint>

#define NE    8192
#define DIM   128
#define PMAX  5
#define NNODE 512
#define TOTAL (NNODE * NNODE)

#define G_CTAS       64
#define THREADS      1024
#define PAIRS_CTA    (TOTAL / G_CTAS)        // 4096
#define TBL_BYTES    (PMAX * NE * 4)         // 163840
#define CHUNK_BYTES  (NE * 4)                // 32768 (one p slice)
#define PHASE_PAIRS  2048
#define PHASE_BYTES  (PHASE_PAIRS * PMAX * 4) // 40960
#define SMEM_BYTES   (TBL_BYTES + PHASE_BYTES) // 204800

// Precomputed dot products, layout [p][e].
__device__ float g_dots[PMAX * NE];

__device__ __forceinline__ uint32_t smem_u32(const void* p) {
    return (uint32_t)__cvta_generic_to_shared(p);
}

__device__ __forceinline__ void mbar_init(uint32_t mb) {
    asm volatile("mbarrier.init.shared.b64 [%0], 1;" :: "r"(mb));
}

__device__ __forceinline__ void mbar_wait(uint32_t mb) {
    uint32_t done;
    asm volatile(
        "{\n\t.reg .pred p;\n\t"
        "mbarrier.try_wait.parity.acquire.cta.shared::cta.b64 p, [%1], 0;\n\t"
        "selp.b32 %0, 1, 0, p;\n\t}"
        : "=r"(done) : "r"(mb) : "memory");
    while (!done) {
        asm volatile(
            "{\n\t.reg .pred p;\n\t"
            "mbarrier.try_wait.parity.acquire.cta.shared::cta.b64 p, [%1], 0, 0x989680;\n\t"
            "selp.b32 %0, 1, 0, p;\n\t}"
            : "=r"(done) : "r"(mb) : "memory");
    }
}

__device__ __forceinline__ void bulk_copy(uint32_t dst, const void* src,
                                          uint32_t bytes, uint32_t mb) {
    asm volatile(
        "cp.async.bulk.shared::cta.global.mbarrier::complete_tx::bytes "
        "[%0], [%1], %2, [%3];"
        :: "r"(dst), "l"(src), "r"(bytes), "r"(mb) : "memory");
}

// ---------------------------------------------------------------------------
// Kernel 1: dots[p][e] = sum_d emb[e][d] * ev[p][d]
// 1024 CTAs x 256 threads, one warp per edge: max MLP, single wave.
// ---------------------------------------------------------------------------
__global__ __launch_bounds__(256) void edge_dot_kernel(
        const float* __restrict__ emb, const float* __restrict__ ev) {
    const int lane = threadIdx.x & 31;
    const int e    = (blockIdx.x * 256 + threadIdx.x) >> 5;

    float4 a = __ldg(((const float4*)emb) + e * (DIM / 4) + lane);

    float4 evr[PMAX];
#pragma unroll
    for (int p = 0; p < PMAX; ++p)
        evr[p] = __ldg(((const float4*)ev) + p * (DIM / 4) + lane);

    float part[PMAX];
#pragma unroll
    for (int p = 0; p < PMAX; ++p)
        part[p] = a.x * evr[p].x + a.y * evr[p].y +
                  a.z * evr[p].z + a.w * evr[p].w;

#pragma unroll
    for (int off = 16; off > 0; off >>= 1) {
#pragma unroll
        for (int p = 0; p < PMAX; ++p)
            part[p] += __shfl_xor_sync(0xffffffffu, part[p], off);
    }

    if (lane == 0) {
#pragma unroll
        for (int p = 0; p < PMAX; ++p)
            g_dots[p * NE + e] = part[p];
    }
}

// ---------------------------------------------------------------------------
// Kernel 2: 64 CTAs x 1024 threads x 4 pairs = 262144 exactly.
// Table streamed in 5 per-p chunks (own mbarriers) so the LDS gather
// overlaps the fill. Paths staged in two 40KB phases via one reused buffer.
// ---------------------------------------------------------------------------
__global__ __launch_bounds__(THREADS, 1) void gather_kernel(
        const int* __restrict__ paths, float* __restrict__ out) {
    extern __shared__ __align__(16) char smem[];
    float* s_dots  = (float*)smem;                 // 163840 B
    int*   s_paths = (int*)(smem + TBL_BYTES);     // 40960 B (reused 2x)
    __shared__ __align__(8) unsigned long long mbars[7]; // [0..4]=chunks, 5,6=paths

    const int tid = threadIdx.x;
    uint32_t mbc[PMAX], mbp0, mbp1;
#pragma unroll
    for (int p = 0; p < PMAX; ++p) mbc[p] = smem_u32(&mbars[p]);
    mbp0 = smem_u32(&mbars[5]);
    mbp1 = smem_u32(&mbars[6]);

    if (tid == 0) {
#pragma unroll
        for (int i = 0; i < 7; ++i) mbar_init(smem_u32(&mbars[i]));
    }
    __syncthreads();

    const char* pbase = (const char*)paths + blockIdx.x * (PAIRS_CTA * PMAX * 4);

    if (tid == 0) {
        // paths phase 1 first: indices ready earliest
        asm volatile("mbarrier.arrive.expect_tx.shared.b64 _, [%0], %1;"
                     :: "r"(mbp0), "r"((uint32_t)PHASE_BYTES) : "memory");
        bulk_copy(smem_u32(s_paths), pbase, PHASE_BYTES, mbp0);

        // table: 5 chunks, one per p
#pragma unroll
        for (int p = 0; p < PMAX; ++p) {
            asm volatile("mbarrier.arrive.expect_tx.shared.b64 _, [%0], %1;"
                         :: "r"(mbc[p]), "r"((uint32_t)CHUNK_BYTES) : "memory");
            bulk_copy(smem_u32(s_dots) + p * CHUNK_BYTES,
                      (const char*)g_dots + p * CHUNK_BYTES,
                      CHUNK_BYTES, mbc[p]);
        }
    }

    // --- phase 1 indices: thread t -> local pairs (2t, 2t+1) ---
    int e[4 * PMAX];
    mbar_wait(mbp0);
#pragma unroll
    for (int k = 0; k < 2 * PMAX; ++k)
        e[k] = s_paths[10 * tid + k];
    __syncthreads();                       // everyone done reading buffer

    if (tid == 0) {
        asm volatile("mbarrier.arrive.expect_tx.shared.b64 _, [%0], %1;"
                     :: "r"(mbp1), "r"((uint32_t)PHASE_BYTES) : "memory");
        bulk_copy(smem_u32(s_paths), pbase + PHASE_BYTES, PHASE_BYTES, mbp1);
    }
    mbar_wait(mbp1);
#pragma unroll
    for (int k = 0; k < 2 * PMAX; ++k)
        e[2 * PMAX + k] = s_paths[10 * tid + k];

    // path-length counts (independent of table)
    int cnt[4] = {0, 0, 0, 0};
#pragma unroll
    for (int j = 0; j < 4; ++j)
#pragma unroll
        for (int p = 0; p < PMAX; ++p)
            if (e[j * PMAX + p] >= 0) ++cnt[j];

    // --- chunked gather: consume p-slice as it lands ---
    float acc[4] = {0.f, 0.f, 0.f, 0.f};
#pragma unroll
    for (int p = 0; p < PMAX; ++p) {
        mbar_wait(mbc[p]);
        const float* tp = s_dots + p * NE;
#pragma unroll
        for (int j = 0; j < 4; ++j) {
            int ei = e[j * PMAX + p];
            if (ei >= 0) acc[j] += tp[ei];
        }
    }

    // --- write: pairs (2t,2t+1) and (2048+2t, 2048+2t+1) ---
    float2 r0, r1;
    r0.x = cnt[0] ? acc[0] / (float)cnt[0] : 0.0f;
    r0.y = cnt[1] ? acc[1] / (float)cnt[1] : 0.0f;
    r1.x = cnt[2] ? acc[2] / (float)cnt[2] : 0.0f;
    r1.y = cnt[3] ? acc[3] / (float)cnt[3] : 0.0f;
    float2* o2 = (float2*)out + blockIdx.x * (PAIRS_CTA / 2);
    o2[tid]        = r0;
    o2[tid + 1024] = r1;
}

// ---------------------------------------------------------------------------
// Launch
// ---------------------------------------------------------------------------
extern "C" void kernel_launch(void* const* d_in, const int* in_sizes, int n_in,
                              void* d_out, int out_size) {
    const float* emb   = nullptr;
    const int*   paths = nullptr;
    const float* ev    = nullptr;
    for (int i = 0; i < n_in; ++i) {
        if (in_sizes[i] == NE * DIM)                  emb   = (const float*)d_in[i];
        else if (in_sizes[i] == NNODE * NNODE * PMAX) paths = (const int*)d_in[i];
        else if (in_sizes[i] == PMAX * DIM)           ev    = (const float*)d_in[i];
    }
    float* out = (float*)d_out;

    edge_dot_kernel<<<NE / 8, 256>>>(emb, ev);   // 1024 CTAs, warp per edge

    cudaFuncSetAttribute(gather_kernel,
                         cudaFuncAttributeMaxDynamicSharedMemorySize,
                         SMEM_BYTES);
    gather_kernel<<<G_CTAS, THREADS, SMEM_BYTES>>>(paths, out);
}

// round 8
// speedup vs baseline: 1.1940x; 1.0239x over previous
#include <cuda_runtime.h>
#include <cstdint>

#define NE    8192
#define DIM   128
#define PMAX  5
#define NNODE 512
#define TOTAL (NNODE * NNODE)

#define G_CTAS       128
#define THREADS      1024
#define PAIRS_CTA    (TOTAL / G_CTAS)          // 2048
#define TBL_BYTES    (PMAX * NE * 4)           // 163840
#define CHUNK_BYTES  (NE * 4)                  // 32768 (one p slice)
#define PATH_BYTES   (PAIRS_CTA * PMAX * 4)    // 40960
#define SMEM_BYTES   (TBL_BYTES + PATH_BYTES)  // 204800

// Precomputed dot products, layout [p][e].
__device__ float g_dots[PMAX * NE];

__device__ __forceinline__ uint32_t smem_u32(const void* p) {
    return (uint32_t)__cvta_generic_to_shared(p);
}

__device__ __forceinline__ void mbar_init(uint32_t mb) {
    asm volatile("mbarrier.init.shared.b64 [%0], 1;" :: "r"(mb));
}

__device__ __forceinline__ void mbar_wait(uint32_t mb) {
    uint32_t done;
    asm volatile(
        "{\n\t.reg .pred p;\n\t"
        "mbarrier.try_wait.parity.acquire.cta.shared::cta.b64 p, [%1], 0;\n\t"
        "selp.b32 %0, 1, 0, p;\n\t}"
        : "=r"(done) : "r"(mb) : "memory");
    while (!done) {
        asm volatile(
            "{\n\t.reg .pred p;\n\t"
            "mbarrier.try_wait.parity.acquire.cta.shared::cta.b64 p, [%1], 0, 0x989680;\n\t"
            "selp.b32 %0, 1, 0, p;\n\t}"
            : "=r"(done) : "r"(mb) : "memory");
    }
}

__device__ __forceinline__ void bulk_copy(uint32_t dst, const void* src,
                                          uint32_t bytes, uint32_t mb) {
    asm volatile(
        "cp.async.bulk.shared::cta.global.mbarrier::complete_tx::bytes "
        "[%0], [%1], %2, [%3];"
        :: "r"(dst), "l"(src), "r"(bytes), "r"(mb) : "memory");
}

// ---------------------------------------------------------------------------
// Kernel 1: dots[p][e] = sum_d emb[e][d] * ev[p][d]
// 1024 CTAs x 256 threads, one warp per edge (fastest measured variant).
// ---------------------------------------------------------------------------
__global__ __launch_bounds__(256) void edge_dot_kernel(
        const float* __restrict__ emb, const float* __restrict__ ev) {
    const int lane = threadIdx.x & 31;
    const int e    = (blockIdx.x * 256 + threadIdx.x) >> 5;

    float4 a = __ldg(((const float4*)emb) + e * (DIM / 4) + lane);

    float4 evr[PMAX];
#pragma unroll
    for (int p = 0; p < PMAX; ++p)
        evr[p] = __ldg(((const float4*)ev) + p * (DIM / 4) + lane);

    float part[PMAX];
#pragma unroll
    for (int p = 0; p < PMAX; ++p)
        part[p] = a.x * evr[p].x + a.y * evr[p].y +
                  a.z * evr[p].z + a.w * evr[p].w;

#pragma unroll
    for (int off = 16; off > 0; off >>= 1) {
#pragma unroll
        for (int p = 0; p < PMAX; ++p)
            part[p] += __shfl_xor_sync(0xffffffffu, part[p], off);
    }

    if (lane == 0) {
#pragma unroll
        for (int p = 0; p < PMAX; ++p)
            g_dots[p * NE + e] = part[p];
    }
}

// ---------------------------------------------------------------------------
// Kernel 2: 128 CTAs x 1024 threads x 2 pairs = 262144 exactly.
// Zero LDGs. Table streamed in 5 per-p chunks (own mbarriers) so the gather
// overlaps the fill. Pair mapping: thread t -> pairs t and t+1024 (stride-5
// index words: conflict-free LDS; coalesced STG.32 output).
// ---------------------------------------------------------------------------
__global__ __launch_bounds__(THREADS, 1) void gather_kernel(
        const int* __restrict__ paths, float* __restrict__ out) {
    extern __shared__ __align__(16) char smem[];
    float* s_dots  = (float*)smem;                 // 163840 B
    int*   s_paths = (int*)(smem + TBL_BYTES);     // 40960 B
    __shared__ __align__(8) unsigned long long mbars[6]; // [0..4]=chunks, 5=paths

    const int tid = threadIdx.x;
    uint32_t mbc[PMAX];
#pragma unroll
    for (int p = 0; p < PMAX; ++p) mbc[p] = smem_u32(&mbars[p]);
    const uint32_t mbp = smem_u32(&mbars[5]);

    if (tid == 0) {
#pragma unroll
        for (int i = 0; i < 6; ++i) mbar_init(smem_u32(&mbars[i]));
    }
    __syncthreads();

    if (tid == 0) {
        // paths slice first: indices needed earliest
        asm volatile("mbarrier.arrive.expect_tx.shared.b64 _, [%0], %1;"
                     :: "r"(mbp), "r"((uint32_t)PATH_BYTES) : "memory");
        bulk_copy(smem_u32(s_paths),
                  (const char*)paths + blockIdx.x * PATH_BYTES,
                  PATH_BYTES, mbp);
        // dots table: one chunk per p
#pragma unroll
        for (int p = 0; p < PMAX; ++p) {
            asm volatile("mbarrier.arrive.expect_tx.shared.b64 _, [%0], %1;"
                         :: "r"(mbc[p]), "r"((uint32_t)CHUNK_BYTES) : "memory");
            bulk_copy(smem_u32(s_dots) + p * CHUNK_BYTES,
                      (const char*)g_dots + p * CHUNK_BYTES,
                      CHUNK_BYTES, mbc[p]);
        }
    }

    // --- indices: thread t -> pairs t and t+1024; stride-5 = conflict-free
    mbar_wait(mbp);
    int e0[PMAX], e1[PMAX];
#pragma unroll
    for (int p = 0; p < PMAX; ++p) e0[p] = s_paths[5 * tid + p];
#pragma unroll
    for (int p = 0; p < PMAX; ++p) e1[p] = s_paths[5 * (tid + 1024) + p];

    int c0 = 0, c1 = 0;
#pragma unroll
    for (int p = 0; p < PMAX; ++p) { if (e0[p] >= 0) ++c0; if (e1[p] >= 0) ++c1; }

    // --- chunked gather: consume each p-slice as it lands
    float a0 = 0.f, a1 = 0.f;
#pragma unroll
    for (int p = 0; p < PMAX; ++p) {
        mbar_wait(mbc[p]);
        const float* tp = s_dots + p * NE;
        if (e0[p] >= 0) a0 += tp[e0[p]];
        if (e1[p] >= 0) a1 += tp[e1[p]];
    }

    float* ob = out + blockIdx.x * PAIRS_CTA;
    ob[tid]        = c0 ? a0 / (float)c0 : 0.0f;
    ob[tid + 1024] = c1 ? a1 / (float)c1 : 0.0f;
}

// ---------------------------------------------------------------------------
// Launch
// ---------------------------------------------------------------------------
extern "C" void kernel_launch(void* const* d_in, const int* in_sizes, int n_in,
                              void* d_out, int out_size) {
    const float* emb   = nullptr;
    const int*   paths = nullptr;
    const float* ev    = nullptr;
    for (int i = 0; i < n_in; ++i) {
        if (in_sizes[i] == NE * DIM)                  emb   = (const float*)d_in[i];
        else if (in_sizes[i] == NNODE * NNODE * PMAX) paths = (const int*)d_in[i];
        else if (in_sizes[i] == PMAX * DIM)           ev    = (const float*)d_in[i];
    }
    float* out = (float*)d_out;

    edge_dot_kernel<<<NE / 8, 256>>>(emb, ev);

    cudaFuncSetAttribute(gather_kernel,
                         cudaFuncAttributeMaxDynamicSharedMemorySize,
                         SMEM_BYTES);
    gather_kernel<<<G_CTAS, THREADS, SMEM_BYTES>>>(paths, out);
}